// round 3
// baseline (speedup 1.0000x reference)
#include <cuda_runtime.h>
#include <math.h>

#define WW 512
#define HH 512
#define NIMG 8
#define HWSZ (HH * WW)
#define NPLANES 16            // 2 streams (p, target) x 8 samples
#define TOTALSZ (NPLANES * HWSZ)
#define NITER 50

// Static scratch (no allocations allowed in kernel_launch)
__device__ float g_p[NIMG * HWSZ];     // sigmoid(output), kept for final reduction
__device__ float g_imgA[TOTALSZ];      // ping
__device__ float g_imgB[TOTALSZ];      // pong
__device__ float g_skel[TOTALSZ];      // skeleton accumulators (both streams)
__device__ double g_sums[NIMG][7];     // per-sample reduction accumulators

// ---------------------------------------------------------------------------
// Init: p = sigmoid(output); imgA[stream0] = p, imgA[stream1] = target
// ---------------------------------------------------------------------------
__global__ void k_init(const float* __restrict__ out, const float* __restrict__ tgt) {
    int i = blockIdx.x * blockDim.x + threadIdx.x;
    int stride = gridDim.x * blockDim.x;
    for (; i < NIMG * HWSZ; i += stride) {
        float v = 1.0f / (1.0f + expf(-out[i]));
        g_p[i] = v;
        g_imgA[i] = v;
        g_imgA[NIMG * HWSZ + i] = tgt[i];
    }
}

// ---------------------------------------------------------------------------
// skel = relu(img - dilate(erode(img)))   (halo-2 fused open; img unchanged)
// erode OOB sentinel = +inf, dilate OOB sentinel = -inf
// ---------------------------------------------------------------------------
__global__ void k_open_init() {
    __shared__ float sI[36][40];  // img tile, OOB = +inf (consumer: erode)
    __shared__ float sE[34][40];  // erode(img), OOB = -inf (consumer: dilate)

    const int z = blockIdx.z;
    const float* __restrict__ src = g_imgA + z * HWSZ;
    float* __restrict__ skel = g_skel + z * HWSZ;

    const int gx0 = blockIdx.x * 32 - 2;
    const int gy0 = blockIdx.y * 32 - 2;
    const int tid = threadIdx.y * 32 + threadIdx.x;

    for (int idx = tid; idx < 36 * 36; idx += 1024) {
        int r = idx / 36, c = idx % 36;
        int gy = gy0 + r, gx = gx0 + c;
        sI[r][c] = ((unsigned)gy < HH && (unsigned)gx < WW) ? src[gy * WW + gx] : INFINITY;
    }
    __syncthreads();

    for (int idx = tid; idx < 34 * 34; idx += 1024) {
        int r = idx / 34, c = idx % 34;
        int gy = gy0 + 1 + r, gx = gx0 + 1 + c;
        float v = -INFINITY;
        if ((unsigned)gy < HH && (unsigned)gx < WW) {
            float pv = fminf(sI[r][c + 1], fminf(sI[r + 1][c + 1], sI[r + 2][c + 1]));
            float ph = fminf(sI[r + 1][c], fminf(sI[r + 1][c + 1], sI[r + 1][c + 2]));
            v = fminf(pv, ph);
        }
        sE[r][c] = v;
    }
    __syncthreads();

    const int ty = threadIdx.y, tx = threadIdx.x;
    float d = -INFINITY;
#pragma unroll
    for (int dr = 0; dr < 3; dr++)
#pragma unroll
        for (int dc = 0; dc < 3; dc++)
            d = fmaxf(d, sE[ty + dr][tx + dc]);

    float img = sI[ty + 2][tx + 2];
    int gy = gy0 + 2 + ty, gx = gx0 + 2 + tx;
    skel[gy * WW + gx] = fmaxf(0.0f, img - d);
}

// ---------------------------------------------------------------------------
// One full skeleton iteration, fused (halo 3):
//   E1 = erode(img)          -> new img
//   E2 = erode(E1)
//   D  = dilate(E2)
//   delta = relu(E1 - D); skel += relu(delta - skel*delta)
// ---------------------------------------------------------------------------
__global__ void k_iter(int flip) {
    __shared__ float sI[38][40];   // img, OOB = +inf
    __shared__ float sE1[36][40];  // erode(img), OOB = +inf (consumer: erode)
    __shared__ float sE2[34][40];  // erode(E1), OOB = -inf (consumer: dilate)

    const int z = blockIdx.z;
    const float* __restrict__ src = (flip ? g_imgB : g_imgA) + z * HWSZ;
    float* __restrict__ dst = (flip ? g_imgA : g_imgB) + z * HWSZ;
    float* __restrict__ skel = g_skel + z * HWSZ;

    const int gx0 = blockIdx.x * 32 - 3;
    const int gy0 = blockIdx.y * 32 - 3;
    const int tid = threadIdx.y * 32 + threadIdx.x;

    for (int idx = tid; idx < 38 * 38; idx += 1024) {
        int r = idx / 38, c = idx % 38;
        int gy = gy0 + r, gx = gx0 + c;
        sI[r][c] = ((unsigned)gy < HH && (unsigned)gx < WW) ? src[gy * WW + gx] : INFINITY;
    }
    __syncthreads();

    for (int idx = tid; idx < 36 * 36; idx += 1024) {
        int r = idx / 36, c = idx % 36;
        int gy = gy0 + 1 + r, gx = gx0 + 1 + c;
        float v = INFINITY;
        if ((unsigned)gy < HH && (unsigned)gx < WW) {
            float pv = fminf(sI[r][c + 1], fminf(sI[r + 1][c + 1], sI[r + 2][c + 1]));
            float ph = fminf(sI[r + 1][c], fminf(sI[r + 1][c + 1], sI[r + 1][c + 2]));
            v = fminf(pv, ph);
        }
        sE1[r][c] = v;
    }
    __syncthreads();

    for (int idx = tid; idx < 34 * 34; idx += 1024) {
        int r = idx / 34, c = idx % 34;
        int gy = gy0 + 2 + r, gx = gx0 + 2 + c;
        float v = -INFINITY;
        if ((unsigned)gy < HH && (unsigned)gx < WW) {
            float pv = fminf(sE1[r][c + 1], fminf(sE1[r + 1][c + 1], sE1[r + 2][c + 1]));
            float ph = fminf(sE1[r + 1][c], fminf(sE1[r + 1][c + 1], sE1[r + 1][c + 2]));
            v = fminf(pv, ph);
        }
        sE2[r][c] = v;
    }
    __syncthreads();

    const int ty = threadIdx.y, tx = threadIdx.x;
    float d = -INFINITY;
#pragma unroll
    for (int dr = 0; dr < 3; dr++)
#pragma unroll
        for (int dc = 0; dc < 3; dc++)
            d = fmaxf(d, sE2[ty + dr][tx + dc]);

    float e1c = sE1[ty + 2][tx + 2];          // eroded img = new img
    float delta = fmaxf(0.0f, e1c - d);

    int g = (gy0 + 3 + ty) * WW + (gx0 + 3 + tx);
    float s = skel[g];
    skel[g] = s + fmaxf(0.0f, delta - s * delta);
    dst[g] = e1c;
}

// ---------------------------------------------------------------------------
// Reductions
// ---------------------------------------------------------------------------
__global__ void k_zero() {
    int t = threadIdx.x;
    if (t < NIMG * 7) ((double*)g_sums)[t] = 0.0;
}

__global__ void k_reduce(const float* __restrict__ tgt) {
    const int n = blockIdx.y;
    const float* __restrict__ sp = g_skel + n * HWSZ;
    const float* __restrict__ sl = g_skel + (NIMG + n) * HWSZ;
    const float* __restrict__ pp = g_p + n * HWSZ;
    const float* __restrict__ tt = tgt + n * HWSZ;

    double a0 = 0, a1 = 0, a2 = 0, a3 = 0, a4 = 0, a5 = 0, a6 = 0;
    for (int i = blockIdx.x * blockDim.x + threadIdx.x; i < HWSZ;
         i += gridDim.x * blockDim.x) {
        float s1 = sp[i], s2 = sl[i], pv = pp[i], tv = tt[i];
        a0 += (double)(s1 * tv);
        a1 += (double)s1;
        a2 += (double)(s2 * pv);
        a3 += (double)s2;
        a4 += (double)(pv * tv);
        a5 += (double)pv;
        a6 += (double)tv;
    }
#pragma unroll
    for (int o = 16; o > 0; o >>= 1) {
        a0 += __shfl_down_sync(0xffffffffu, a0, o);
        a1 += __shfl_down_sync(0xffffffffu, a1, o);
        a2 += __shfl_down_sync(0xffffffffu, a2, o);
        a3 += __shfl_down_sync(0xffffffffu, a3, o);
        a4 += __shfl_down_sync(0xffffffffu, a4, o);
        a5 += __shfl_down_sync(0xffffffffu, a5, o);
        a6 += __shfl_down_sync(0xffffffffu, a6, o);
    }
    if ((threadIdx.x & 31) == 0) {
        atomicAdd(&g_sums[n][0], a0);
        atomicAdd(&g_sums[n][1], a1);
        atomicAdd(&g_sums[n][2], a2);
        atomicAdd(&g_sums[n][3], a3);
        atomicAdd(&g_sums[n][4], a4);
        atomicAdd(&g_sums[n][5], a5);
        atomicAdd(&g_sums[n][6], a6);
    }
}

__global__ void k_final(float* __restrict__ out, int out_size) {
    if (threadIdx.x == 0 && blockIdx.x == 0) {
        const double smooth = 1.0;
        double cl = 0.0, dice = 0.0;
        for (int n = 0; n < NIMG; n++) {
            double A = g_sums[n][0], B = g_sums[n][1], C = g_sums[n][2],
                   D = g_sums[n][3], E = g_sums[n][4], F = g_sums[n][5],
                   G = g_sums[n][6];
            double tprec = (A + smooth) / (B + smooth);
            double tsens = (C + smooth) / (D + smooth);
            cl += 1.0 - 2.0 * tprec * tsens / (tprec + tsens);
            dice += 1.0 - 2.0 * (E + smooth) / (F + G + smooth);
        }
        cl /= NIMG;
        dice /= NIMG;
        float loss = (float)(0.7 * dice + 0.3 * cl);
        for (int i = 0; i < out_size; i++) out[i] = loss;
    }
}

// ---------------------------------------------------------------------------
extern "C" void kernel_launch(void* const* d_in, const int* in_sizes, int n_in,
                              void* d_out, int out_size) {
    const float* output = (const float*)d_in[0];
    const float* target = (const float*)d_in[1];
    float* out = (float*)d_out;

    k_init<<<2048, 256>>>(output, target);

    dim3 blk(32, 32);
    dim3 grd(WW / 32, HH / 32, NPLANES);
    k_open_init<<<grd, blk>>>();

    for (int it = 0; it < NITER; ++it) {
        k_iter<<<grd, blk>>>(it & 1);
    }

    k_zero<<<1, 64>>>();
    k_reduce<<<dim3(32, NIMG), 256>>>(target);
    k_final<<<1, 32>>>(out, out_size);
}

// round 4
// speedup vs baseline: 1.4062x; 1.4062x over previous
#include <cuda_runtime.h>
#include <math.h>

#define WW 512
#define HH 512
#define NIMG 8
#define HWSZ (HH * WW)
#define NPLANES 16            // 2 streams (p, target) x 8 samples
#define TOTALSZ (NPLANES * HWSZ)
#define NITER 50

// Static scratch (no allocations allowed in kernel_launch)
__device__ float g_p[NIMG * HWSZ];     // sigmoid(output), kept for final reduction
__device__ float g_imgA[TOTALSZ];      // ping
__device__ float g_imgB[TOTALSZ];      // pong
__device__ float g_skel[TOTALSZ];      // skeleton accumulators (both streams)
__device__ double g_sums[NIMG][7];     // per-sample reduction accumulators

// ---------------------------------------------------------------------------
// Init: p = sigmoid(output); imgA[stream0] = p, imgA[stream1] = target
// ---------------------------------------------------------------------------
__global__ void k_init(const float4* __restrict__ out, const float4* __restrict__ tgt) {
    int i = blockIdx.x * blockDim.x + threadIdx.x;
    int stride = gridDim.x * blockDim.x;
    float4* gp = (float4*)g_p;
    float4* ga = (float4*)g_imgA;
    float4* gb = (float4*)(g_imgA + NIMG * HWSZ);
    const int n4 = NIMG * HWSZ / 4;
    for (; i < n4; i += stride) {
        float4 o = out[i];
        float4 v;
        v.x = 1.0f / (1.0f + expf(-o.x));
        v.y = 1.0f / (1.0f + expf(-o.y));
        v.z = 1.0f / (1.0f + expf(-o.z));
        v.w = 1.0f / (1.0f + expf(-o.w));
        gp[i] = v;
        ga[i] = v;
        gb[i] = tgt[i];
    }
}

// ---------------------------------------------------------------------------
// skel = relu(img - dilate(erode(img)))   (halo-2 fused open; img unchanged)
// ---------------------------------------------------------------------------
__global__ void k_open_init() {
    __shared__ float sI[36][40];  // img tile, OOB = +inf (consumer: erode)
    __shared__ float sE[34][40];  // erode(img), OOB = -inf (consumer: dilate)

    const int z = blockIdx.z;
    const float* __restrict__ src = g_imgA + z * HWSZ;
    float* __restrict__ skel = g_skel + z * HWSZ;

    const int gx0 = blockIdx.x * 32 - 2;
    const int gy0 = blockIdx.y * 32 - 2;
    const int tid = threadIdx.y * 32 + threadIdx.x;

    for (int idx = tid; idx < 36 * 36; idx += 1024) {
        int r = idx / 36, c = idx % 36;
        int gy = gy0 + r, gx = gx0 + c;
        sI[r][c] = ((unsigned)gy < HH && (unsigned)gx < WW) ? src[gy * WW + gx] : INFINITY;
    }
    __syncthreads();

    for (int idx = tid; idx < 34 * 34; idx += 1024) {
        int r = idx / 34, c = idx % 34;
        int gy = gy0 + 1 + r, gx = gx0 + 1 + c;
        float v = -INFINITY;
        if ((unsigned)gy < HH && (unsigned)gx < WW) {
            float pv = fminf(sI[r][c + 1], fminf(sI[r + 1][c + 1], sI[r + 2][c + 1]));
            float ph = fminf(sI[r + 1][c], fminf(sI[r + 1][c + 1], sI[r + 1][c + 2]));
            v = fminf(pv, ph);
        }
        sE[r][c] = v;
    }
    __syncthreads();

    const int ty = threadIdx.y, tx = threadIdx.x;
    float d = -INFINITY;
#pragma unroll
    for (int dr = 0; dr < 3; dr++)
#pragma unroll
        for (int dc = 0; dc < 3; dc++)
            d = fmaxf(d, sE[ty + dr][tx + dc]);

    float img = sI[ty + 2][tx + 2];
    int gy = gy0 + 2 + ty, gx = gx0 + 2 + tx;
    skel[gy * WW + gx] = fmaxf(0.0f, img - d);
}

// ---------------------------------------------------------------------------
// One full skeleton iteration, fused, vectorized (float2), 64x32 tile, halo 3.
//   E1 = erode(img) -> new img; E2 = erode(E1); D = dilate(E2) (separable);
//   delta = relu(E1 - D); skel += relu(delta - skel*delta)
// Shared col index u <-> global gx = gx0 - 4 + u  (stride 72, pairs 8B-aligned)
// Shared row: sI row r <-> gy0-3+r; sE1 row t <-> gy0-2+t; sE2 row s <-> gy0-1+s
// ---------------------------------------------------------------------------
template<bool IN>
__device__ __forceinline__ void iter_body(
    const float* __restrict__ src, float* __restrict__ dst,
    float* __restrict__ skel,
    float (*sI)[72], float (*sE1)[72], float (*sE2)[72],
    int gx0, int gy0)
{
    const int tx = threadIdx.x, ty = threadIdx.y;

    // ---- fill sI (38 rows x 72 cols), OOB = +inf --------------------------
    for (int r = ty; r < 38; r += 32) {
        const int gy = gy0 - 3 + r;
        const float* rowp = src + gy * WW;
        const bool rok = IN || ((unsigned)gy < HH);
        {
            const int c = 2 * tx;
            const int gx = gx0 - 4 + c;
            float2 v;
            if (IN || (rok && (unsigned)gx < WW)) v = *(const float2*)(rowp + gx);
            else v = make_float2(INFINITY, INFINITY);
            *(float2*)&sI[r][c] = v;
        }
        if (tx < 4) {
            const int c = 64 + 2 * tx;
            const int gx = gx0 - 4 + c;
            float2 v;
            if (IN || (rok && (unsigned)gx < WW)) v = *(const float2*)(rowp + gx);
            else v = make_float2(INFINITY, INFINITY);
            *(float2*)&sI[r][c] = v;
        }
    }
    __syncthreads();

    // ---- E1 = erode(img): rows t 0..35, col pairs m 1..34 -----------------
    for (int t = ty; t < 36; t += 32) {
        const int gy = gy0 - 2 + t;
        const bool rok = IN || ((unsigned)gy < HH);
        for (int m = tx + 1; m < 35; m += 32) {
            const int c = 2 * m;
            const float2 r0 = *(const float2*)&sI[t][c];
            const float2 r1 = *(const float2*)&sI[t + 1][c];
            const float2 r2 = *(const float2*)&sI[t + 2][c];
            const float L = sI[t + 1][c - 1], R = sI[t + 1][c + 2];
            float vx = fminf(fminf(r0.x, r1.x), r2.x);
            float vy = fminf(fminf(r0.y, r1.y), r2.y);
            const float mab = fminf(r1.x, r1.y);
            float e0 = fminf(vx, fminf(L, mab));
            float e1 = fminf(vy, fminf(mab, R));
            if (!IN) {
                const int gx = gx0 - 4 + c;     // pair fully in/out (gx even)
                if (!(rok && (unsigned)gx < WW)) { e0 = INFINITY; e1 = INFINITY; }
            }
            *(float2*)&sE1[t][c] = make_float2(e0, e1);
        }
        if (tx == 0) { sE1[t][1] = INFINITY; sE1[t][70] = INFINITY; }
    }
    __syncthreads();

    // ---- E2 = erode(E1): rows s 0..33, col pairs m 1..34 ------------------
    for (int s = ty; s < 34; s += 32) {
        const int gy = gy0 - 1 + s;
        const bool rok = IN || ((unsigned)gy < HH);
        for (int m = tx + 1; m < 35; m += 32) {
            const int c = 2 * m;
            const float2 r0 = *(const float2*)&sE1[s][c];
            const float2 r1 = *(const float2*)&sE1[s + 1][c];
            const float2 r2 = *(const float2*)&sE1[s + 2][c];
            const float L = sE1[s + 1][c - 1], R = sE1[s + 1][c + 2];
            float vx = fminf(fminf(r0.x, r1.x), r2.x);
            float vy = fminf(fminf(r0.y, r1.y), r2.y);
            const float mab = fminf(r1.x, r1.y);
            float e0 = fminf(vx, fminf(L, mab));
            float e1 = fminf(vy, fminf(mab, R));
            if (!IN) {
                const int gx = gx0 - 4 + c;
                if (!(rok && (unsigned)gx < WW)) { e0 = -INFINITY; e1 = -INFINITY; }
            }
            *(float2*)&sE2[s][c] = make_float2(e0, e1);
        }
    }
    __syncthreads();

    // ---- H = hmax3(E2): rows s 0..33, col pairs m 2..33 (overlay on sI) ---
    float (*H)[72] = sI;
    {
        const int m = tx + 2, c = 2 * m;
        for (int s = ty; s < 34; s += 32) {
            const float2 a = *(const float2*)&sE2[s][c];
            const float L = sE2[s][c - 1], R = sE2[s][c + 2];
            const float mab = fmaxf(a.x, a.y);
            *(float2*)&H[s][c] = make_float2(fmaxf(L, mab), fmaxf(mab, R));
        }
    }
    __syncthreads();

    // ---- D = vmax3(H); delta; skel update; write new img ------------------
    {
        const int q = ty;
        const int c = 2 * (tx + 2);
        const float2 h0 = *(const float2*)&H[q][c];
        const float2 h1 = *(const float2*)&H[q + 1][c];
        const float2 h2 = *(const float2*)&H[q + 2][c];
        const float dx = fmaxf(fmaxf(h0.x, h1.x), h2.x);
        const float dy = fmaxf(fmaxf(h0.y, h1.y), h2.y);
        const float2 e1c = *(const float2*)&sE1[q + 2][c];
        const float d0 = fmaxf(0.0f, e1c.x - dx);
        const float d1 = fmaxf(0.0f, e1c.y - dy);
        const int g = (gy0 + q) * WW + (gx0 + 2 * tx);
        float2 s2 = *(float2*)(skel + g);
        s2.x += fmaxf(0.0f, d0 - s2.x * d0);
        s2.y += fmaxf(0.0f, d1 - s2.y * d1);
        *(float2*)(skel + g) = s2;
        *(float2*)(dst + g) = e1c;
    }
}

__global__ void __launch_bounds__(1024, 2) k_iter(int flip) {
    __shared__ float sI[38][72];
    __shared__ float sE1[36][72];
    __shared__ float sE2[34][72];

    const int z = blockIdx.z;
    const float* __restrict__ src = (flip ? g_imgB : g_imgA) + z * HWSZ;
    float* __restrict__ dst = (flip ? g_imgA : g_imgB) + z * HWSZ;
    float* __restrict__ skel = g_skel + z * HWSZ;

    const int gx0 = blockIdx.x * 64;
    const int gy0 = blockIdx.y * 32;

    const bool interior = (blockIdx.x >= 1) & (blockIdx.x <= 6) &
                          (blockIdx.y >= 1) & (blockIdx.y <= 14);
    if (interior)
        iter_body<true>(src, dst, skel, sI, sE1, sE2, gx0, gy0);
    else
        iter_body<false>(src, dst, skel, sI, sE1, sE2, gx0, gy0);
}

// ---------------------------------------------------------------------------
// Reductions
// ---------------------------------------------------------------------------
__global__ void k_zero() {
    int t = threadIdx.x;
    if (t < NIMG * 7) ((double*)g_sums)[t] = 0.0;
}

__global__ void k_reduce(const float* __restrict__ tgt) {
    const int n = blockIdx.y;
    const float4* __restrict__ sp = (const float4*)(g_skel + n * HWSZ);
    const float4* __restrict__ sl = (const float4*)(g_skel + (NIMG + n) * HWSZ);
    const float4* __restrict__ pp = (const float4*)(g_p + n * HWSZ);
    const float4* __restrict__ tt = (const float4*)(tgt + n * HWSZ);
    const int n4 = HWSZ / 4;

    double a0 = 0, a1 = 0, a2 = 0, a3 = 0, a4 = 0, a5 = 0, a6 = 0;
    for (int i = blockIdx.x * blockDim.x + threadIdx.x; i < n4;
         i += gridDim.x * blockDim.x) {
        float4 s1 = sp[i], s2 = sl[i], pv = pp[i], tv = tt[i];
        a0 += (double)(s1.x * tv.x + s1.y * tv.y + s1.z * tv.z + s1.w * tv.w);
        a1 += (double)(s1.x + s1.y + s1.z + s1.w);
        a2 += (double)(s2.x * pv.x + s2.y * pv.y + s2.z * pv.z + s2.w * pv.w);
        a3 += (double)(s2.x + s2.y + s2.z + s2.w);
        a4 += (double)(pv.x * tv.x + pv.y * tv.y + pv.z * tv.z + pv.w * tv.w);
        a5 += (double)(pv.x + pv.y + pv.z + pv.w);
        a6 += (double)(tv.x + tv.y + tv.z + tv.w);
    }
#pragma unroll
    for (int o = 16; o > 0; o >>= 1) {
        a0 += __shfl_down_sync(0xffffffffu, a0, o);
        a1 += __shfl_down_sync(0xffffffffu, a1, o);
        a2 += __shfl_down_sync(0xffffffffu, a2, o);
        a3 += __shfl_down_sync(0xffffffffu, a3, o);
        a4 += __shfl_down_sync(0xffffffffu, a4, o);
        a5 += __shfl_down_sync(0xffffffffu, a5, o);
        a6 += __shfl_down_sync(0xffffffffu, a6, o);
    }
    if ((threadIdx.x & 31) == 0) {
        atomicAdd(&g_sums[n][0], a0);
        atomicAdd(&g_sums[n][1], a1);
        atomicAdd(&g_sums[n][2], a2);
        atomicAdd(&g_sums[n][3], a3);
        atomicAdd(&g_sums[n][4], a4);
        atomicAdd(&g_sums[n][5], a5);
        atomicAdd(&g_sums[n][6], a6);
    }
}

__global__ void k_final(float* __restrict__ out, int out_size) {
    if (threadIdx.x == 0 && blockIdx.x == 0) {
        const double smooth = 1.0;
        double cl = 0.0, dice = 0.0;
        for (int n = 0; n < NIMG; n++) {
            double A = g_sums[n][0], B = g_sums[n][1], C = g_sums[n][2],
                   D = g_sums[n][3], E = g_sums[n][4], F = g_sums[n][5],
                   G = g_sums[n][6];
            double tprec = (A + smooth) / (B + smooth);
            double tsens = (C + smooth) / (D + smooth);
            cl += 1.0 - 2.0 * tprec * tsens / (tprec + tsens);
            dice += 1.0 - 2.0 * (E + smooth) / (F + G + smooth);
        }
        cl /= NIMG;
        dice /= NIMG;
        float loss = (float)(0.7 * dice + 0.3 * cl);
        for (int i = 0; i < out_size; i++) out[i] = loss;
    }
}

// ---------------------------------------------------------------------------
extern "C" void kernel_launch(void* const* d_in, const int* in_sizes, int n_in,
                              void* d_out, int out_size) {
    const float* output = (const float*)d_in[0];
    const float* target = (const float*)d_in[1];
    float* out = (float*)d_out;

    k_init<<<1024, 256>>>((const float4*)output, (const float4*)target);

    dim3 blk(32, 32);
    k_open_init<<<dim3(16, 16, NPLANES), blk>>>();

    dim3 grd(WW / 64, HH / 32, NPLANES);
    for (int it = 0; it < NITER; ++it) {
        k_iter<<<grd, blk>>>(it & 1);
    }

    k_zero<<<1, 64>>>();
    k_reduce<<<dim3(32, NIMG), 256>>>(target);
    k_final<<<1, 32>>>(out, out_size);
}

// round 6
// speedup vs baseline: 2.5858x; 1.8389x over previous
#include <cuda_runtime.h>
#include <math.h>

#define WW 512
#define HH 512
#define NIMG 8
#define HWSZ (HH * WW)
#define NPLANES 16            // 2 streams (p, target) x 8 samples
#define TOTALSZ (NPLANES * HWSZ)
#define NITER 50

#define STRIPS 5              // 5 strips x 120 output cols (lanes 1..30 of 32x float4)
#define CHUNK_ROWS 16
#define CHUNKS 32             // 512 / 16
#define WARPS_TOTAL (STRIPS * CHUNKS * NPLANES)   // 2560
#define SWEEP_BLOCK 256
#define SWEEP_GRID (WARPS_TOTAL / (SWEEP_BLOCK / 32))  // 320

// Static scratch (no allocations allowed in kernel_launch)
__device__ float g_p[NIMG * HWSZ];     // sigmoid(output), kept for final reduction
__device__ float g_imgA[TOTALSZ];      // ping
__device__ float g_imgB[TOTALSZ];      // pong
__device__ float g_skel[TOTALSZ];      // skeleton accumulators (both streams)
__device__ double g_sums[NIMG][7];     // per-sample reduction accumulators

// ---------------------------------------------------------------------------
// small helpers
// ---------------------------------------------------------------------------
__device__ __forceinline__ float4 f44(float v) { return make_float4(v, v, v, v); }

__device__ __forceinline__ float4 min4(float4 a, float4 b) {
    return make_float4(fminf(a.x, b.x), fminf(a.y, b.y), fminf(a.z, b.z), fminf(a.w, b.w));
}
__device__ __forceinline__ float4 max4(float4 a, float4 b) {
    return make_float4(fmaxf(a.x, b.x), fmaxf(a.y, b.y), fmaxf(a.z, b.z), fmaxf(a.w, b.w));
}
__device__ __forceinline__ float4 vmin3(float4 a, float4 b, float4 c) { return min4(min4(a, b), c); }
__device__ __forceinline__ float4 vmax3(float4 a, float4 b, float4 c) { return max4(max4(a, b), c); }

// horizontal 3-tap min across the warp-wide row (lane holds 4 adjacent cols)
__device__ __forceinline__ float4 hmin3(float4 v, int lane) {
    float L = __shfl_up_sync(0xffffffffu, v.w, 1);
    float R = __shfl_down_sync(0xffffffffu, v.x, 1);
    if (lane == 0)  L = INFINITY;
    if (lane == 31) R = INFINITY;
    float m01 = fminf(v.x, v.y), m23 = fminf(v.z, v.w);
    return make_float4(fminf(L, m01), fminf(m01, v.z), fminf(v.y, m23), fminf(m23, R));
}
__device__ __forceinline__ float4 hmax3(float4 v, int lane) {
    float L = __shfl_up_sync(0xffffffffu, v.w, 1);
    float R = __shfl_down_sync(0xffffffffu, v.x, 1);
    if (lane == 0)  L = -INFINITY;
    if (lane == 31) R = -INFINITY;
    float m01 = fmaxf(v.x, v.y), m23 = fmaxf(v.z, v.w);
    return make_float4(fmaxf(L, m01), fmaxf(m01, v.z), fmaxf(v.y, m23), fmaxf(m23, R));
}

// ---------------------------------------------------------------------------
// Init: p = sigmoid(output); imgA[stream0] = p, imgA[stream1] = target
// ---------------------------------------------------------------------------
__global__ void k_init(const float4* __restrict__ out, const float4* __restrict__ tgt) {
    int i = blockIdx.x * blockDim.x + threadIdx.x;
    int stride = gridDim.x * blockDim.x;
    float4* gp = (float4*)g_p;
    float4* ga = (float4*)g_imgA;
    float4* gb = (float4*)(g_imgA + NIMG * HWSZ);
    const int n4 = NIMG * HWSZ / 4;
    for (; i < n4; i += stride) {
        float4 o = out[i];
        float4 v;
        v.x = 1.0f / (1.0f + expf(-o.x));
        v.y = 1.0f / (1.0f + expf(-o.y));
        v.z = 1.0f / (1.0f + expf(-o.z));
        v.w = 1.0f / (1.0f + expf(-o.w));
        gp[i] = v;
        ga[i] = v;
        gb[i] = tgt[i];
    }
}

// ---------------------------------------------------------------------------
// Warp-sweep open-init:  skel = relu(img - dilate(erode(img)))
// chain depth 2 (vertical halo 2); per warp: 20 pipeline steps.
// ---------------------------------------------------------------------------
__global__ void __launch_bounds__(SWEEP_BLOCK, 3) k_open_init() {
    const int lane = threadIdx.x & 31;
    const int gw = (blockIdx.x * SWEEP_BLOCK + threadIdx.x) >> 5;
    const int strip = gw % STRIPS;
    const int t = gw / STRIPS;
    const int chunk = t & (CHUNKS - 1);
    const int z = t >> 5;

    const float* __restrict__ src = g_imgA + z * HWSZ;
    float* __restrict__ skel = g_skel + z * HWSZ;

    const int c0 = strip * 120 - 4 + 4 * lane;
    const bool colok = (c0 >= 0) && (c0 < WW);
    const bool stok = (lane >= 1) && (lane <= 30) && (c0 < WW);
    const int r0 = chunk * CHUNK_ROWS;
    const int ylim = r0 + 2;

    int y = r0 - 2;
    const float* srcp = src + y * WW + c0;
    float* const skb = skel + c0;

    float4 ia = f44(INFINITY), ib = f44(INFINITY), ic;
    float4 ha = f44(-INFINITY), hb = f44(-INFINITY), hc;

#define OPEN_STEP(IA, IB, IC, HA, HB, HC)                                      \
    {                                                                          \
        bool ldok = colok && ((unsigned)y < (unsigned)HH);                     \
        IC = ldok ? *(const float4*)srcp : f44(INFINITY);                      \
        float4 e1_ = min4(vmin3(IA, IB, IC), hmin3(IB, lane));                 \
        if (!colok || (unsigned)(y - 1) >= (unsigned)HH) e1_ = f44(-INFINITY); \
        HC = hmax3(e1_, lane);                                                 \
        if (y >= ylim) {                                                       \
            float4 d_ = vmax3(HA, HB, HC);                                     \
            if (stok) {                                                        \
                float4 im = IA;                                                \
                float4 o_;                                                     \
                o_.x = fmaxf(0.0f, im.x - d_.x);                               \
                o_.y = fmaxf(0.0f, im.y - d_.y);                               \
                o_.z = fmaxf(0.0f, im.z - d_.z);                               \
                o_.w = fmaxf(0.0f, im.w - d_.w);                               \
                *(float4*)(skb + (y - 2) * WW) = o_;                           \
            }                                                                  \
        }                                                                      \
        ++y;                                                                   \
        srcp += WW;                                                            \
    }

#pragma unroll 1
    for (int k = 0; k < 6; ++k) {
        OPEN_STEP(ia, ib, ic, ha, hb, hc);
        OPEN_STEP(ib, ic, ia, hb, hc, ha);
        OPEN_STEP(ic, ia, ib, hc, ha, hb);
    }
    OPEN_STEP(ia, ib, ic, ha, hb, hc);
    OPEN_STEP(ib, ic, ia, hb, hc, ha);
#undef OPEN_STEP
}

// ---------------------------------------------------------------------------
// Warp-sweep full skeleton iteration (chain depth 3, vertical halo 3):
//   E1 = erode(img) -> new img; E2 = erode(E1); D = dilate(E2);
//   delta = relu(E1 - D); skel += relu(delta - skel*delta)
// Register rings: I (3 rows), E1 (3 rows), H=hmax3(E2) (3 rows). No smem.
// ---------------------------------------------------------------------------
__global__ void __launch_bounds__(SWEEP_BLOCK, 3) k_iter(int flip) {
    const int lane = threadIdx.x & 31;
    const int gw = (blockIdx.x * SWEEP_BLOCK + threadIdx.x) >> 5;
    const int strip = gw % STRIPS;
    const int t = gw / STRIPS;
    const int chunk = t & (CHUNKS - 1);
    const int z = t >> 5;

    const float* __restrict__ src = (flip ? g_imgB : g_imgA) + z * HWSZ;
    float* __restrict__ dst = (flip ? g_imgA : g_imgB) + z * HWSZ;
    float* __restrict__ skel = g_skel + z * HWSZ;

    const int c0 = strip * 120 - 4 + 4 * lane;
    const bool colok = (c0 >= 0) && (c0 < WW);
    const bool stok = (lane >= 1) && (lane <= 30) && (c0 < WW);
    const int r0 = chunk * CHUNK_ROWS;
    const int ylim = r0 + 3;

    int y = r0 - 3;
    const float* srcp = src + y * WW + c0;
    float* const skb = skel + c0;
    float* const dsb = dst + c0;

    float4 ia = f44(INFINITY), ib = f44(INFINITY), ic;
    float4 ea = f44(INFINITY), eb = f44(INFINITY), ec;
    float4 ha = f44(-INFINITY), hb = f44(-INFINITY), hc;

#define ITER_STEP(IA, IB, IC, EA, EB, EC, HA, HB, HC)                          \
    {                                                                          \
        bool ldok = colok && ((unsigned)y < (unsigned)HH);                     \
        IC = ldok ? *(const float4*)srcp : f44(INFINITY);                      \
        EC = min4(vmin3(IA, IB, IC), hmin3(IB, lane));      /* E1 row y-1 */   \
        if ((unsigned)(y - 1) >= (unsigned)HH) EC = f44(INFINITY);             \
        float4 e2_ = min4(vmin3(EA, EB, EC), hmin3(EB, lane)); /* E2 y-2 */    \
        if (!colok || (unsigned)(y - 2) >= (unsigned)HH) e2_ = f44(-INFINITY); \
        HC = hmax3(e2_, lane);                                                 \
        if (y >= ylim) {                        /* output row r = y-3 */       \
            float4 d_ = vmax3(HA, HB, HC);                                     \
            if (stok) {                                                        \
                float4 dl_;                                                    \
                dl_.x = fmaxf(0.0f, EA.x - d_.x);                              \
                dl_.y = fmaxf(0.0f, EA.y - d_.y);                              \
                dl_.z = fmaxf(0.0f, EA.z - d_.z);                              \
                dl_.w = fmaxf(0.0f, EA.w - d_.w);                              \
                float* sk_ = skb + (y - 3) * WW;                               \
                float4 s_ = *(float4*)sk_;                                     \
                s_.x += fmaxf(0.0f, fmaf(-s_.x, dl_.x, dl_.x));                \
                s_.y += fmaxf(0.0f, fmaf(-s_.y, dl_.y, dl_.y));                \
                s_.z += fmaxf(0.0f, fmaf(-s_.z, dl_.z, dl_.z));                \
                s_.w += fmaxf(0.0f, fmaf(-s_.w, dl_.w, dl_.w));                \
                *(float4*)sk_ = s_;                                            \
                *(float4*)(dsb + (y - 3) * WW) = EA;        /* new img */      \
            }                                                                  \
        }                                                                      \
        ++y;                                                                   \
        srcp += WW;                                                            \
    }

#pragma unroll 1
    for (int k = 0; k < 7; ++k) {
        ITER_STEP(ia, ib, ic, ea, eb, ec, ha, hb, hc);
        ITER_STEP(ib, ic, ia, eb, ec, ea, hb, hc, ha);
        ITER_STEP(ic, ia, ib, ec, ea, eb, hc, ha, hb);
    }
    ITER_STEP(ia, ib, ic, ea, eb, ec, ha, hb, hc);
#undef ITER_STEP
}

// ---------------------------------------------------------------------------
// Reductions
// ---------------------------------------------------------------------------
__global__ void k_zero() {
    int t = threadIdx.x;
    if (t < NIMG * 7) ((double*)g_sums)[t] = 0.0;
}

__global__ void k_reduce(const float* __restrict__ tgt) {
    const int n = blockIdx.y;
    const float4* __restrict__ sp = (const float4*)(g_skel + n * HWSZ);
    const float4* __restrict__ sl = (const float4*)(g_skel + (NIMG + n) * HWSZ);
    const float4* __restrict__ pp = (const float4*)(g_p + n * HWSZ);
    const float4* __restrict__ tt = (const float4*)(tgt + n * HWSZ);
    const int n4 = HWSZ / 4;

    double a0 = 0, a1 = 0, a2 = 0, a3 = 0, a4 = 0, a5 = 0, a6 = 0;
    for (int i = blockIdx.x * blockDim.x + threadIdx.x; i < n4;
         i += gridDim.x * blockDim.x) {
        float4 s1 = sp[i], s2 = sl[i], pv = pp[i], tv = tt[i];
        a0 += (double)(s1.x * tv.x + s1.y * tv.y + s1.z * tv.z + s1.w * tv.w);
        a1 += (double)(s1.x + s1.y + s1.z + s1.w);
        a2 += (double)(s2.x * pv.x + s2.y * pv.y + s2.z * pv.z + s2.w * pv.w);
        a3 += (double)(s2.x + s2.y + s2.z + s2.w);
        a4 += (double)(pv.x * tv.x + pv.y * tv.y + pv.z * tv.z + pv.w * tv.w);
        a5 += (double)(pv.x + pv.y + pv.z + pv.w);
        a6 += (double)(tv.x + tv.y + tv.z + tv.w);
    }
#pragma unroll
    for (int o = 16; o > 0; o >>= 1) {
        a0 += __shfl_down_sync(0xffffffffu, a0, o);
        a1 += __shfl_down_sync(0xffffffffu, a1, o);
        a2 += __shfl_down_sync(0xffffffffu, a2, o);
        a3 += __shfl_down_sync(0xffffffffu, a3, o);
        a4 += __shfl_down_sync(0xffffffffu, a4, o);
        a5 += __shfl_down_sync(0xffffffffu, a5, o);
        a6 += __shfl_down_sync(0xffffffffu, a6, o);
    }
    if ((threadIdx.x & 31) == 0) {
        atomicAdd(&g_sums[n][0], a0);
        atomicAdd(&g_sums[n][1], a1);
        atomicAdd(&g_sums[n][2], a2);
        atomicAdd(&g_sums[n][3], a3);
        atomicAdd(&g_sums[n][4], a4);
        atomicAdd(&g_sums[n][5], a5);
        atomicAdd(&g_sums[n][6], a6);
    }
}

__global__ void k_final(float* __restrict__ out, int out_size) {
    if (threadIdx.x == 0 && blockIdx.x == 0) {
        const double smooth = 1.0;
        double cl = 0.0, dice = 0.0;
        for (int n = 0; n < NIMG; n++) {
            double A = g_sums[n][0], B = g_sums[n][1], C = g_sums[n][2],
                   D = g_sums[n][3], E = g_sums[n][4], F = g_sums[n][5],
                   G = g_sums[n][6];
            double tprec = (A + smooth) / (B + smooth);
            double tsens = (C + smooth) / (D + smooth);
            cl += 1.0 - 2.0 * tprec * tsens / (tprec + tsens);
            dice += 1.0 - 2.0 * (E + smooth) / (F + G + smooth);
        }
        cl /= NIMG;
        dice /= NIMG;
        float loss = (float)(0.7 * dice + 0.3 * cl);
        for (int i = 0; i < out_size; i++) out[i] = loss;
    }
}

// ---------------------------------------------------------------------------
extern "C" void kernel_launch(void* const* d_in, const int* in_sizes, int n_in,
                              void* d_out, int out_size) {
    const float* output = (const float*)d_in[0];
    const float* target = (const float*)d_in[1];
    float* out = (float*)d_out;

    k_init<<<1024, 256>>>((const float4*)output, (const float4*)target);

    k_open_init<<<SWEEP_GRID, SWEEP_BLOCK>>>();

    for (int it = 0; it < NITER; ++it) {
        k_iter<<<SWEEP_GRID, SWEEP_BLOCK>>>(it & 1);
    }

    k_zero<<<1, 64>>>();
    k_reduce<<<dim3(32, NIMG), 256>>>(target);
    k_final<<<1, 32>>>(out, out_size);
}

// round 7
// speedup vs baseline: 4.3033x; 1.6642x over previous
#include <cuda_runtime.h>
#include <math.h>

#define WW 512
#define HH 512
#define NIMG 8
#define HWSZ (HH * WW)
#define NPLANES 16            // 2 streams (p, target) x 8 samples
#define TOTALSZ (NPLANES * HWSZ)
#define NITER 50

#define STRIPS 5              // 5 strips x 120 output cols (lanes 1..30 of 32x float4)
#define CHUNK_ROWS 16
#define CHUNKS 32             // 512 / 16
#define WARPS_TOTAL (STRIPS * CHUNKS * NPLANES)   // 2560

// open-init sweep config (unchanged from prior round)
#define SWEEP_BLOCK 256
#define SWEEP_GRID (WARPS_TOTAL / (SWEEP_BLOCK / 32))  // 320

// fused-2 iteration kernel config
#define IT2_BLOCK 128
#define IT2_GRID (WARPS_TOTAL / (IT2_BLOCK / 32))      // 640

// Static scratch (no allocations allowed in kernel_launch)
__device__ float g_p[NIMG * HWSZ];     // sigmoid(output), kept for final reduction
__device__ float g_imgA[TOTALSZ];      // ping
__device__ float g_imgB[TOTALSZ];      // pong
__device__ float g_skel[TOTALSZ];      // skeleton accumulators (both streams)
__device__ double g_sums[NIMG][7];     // per-sample reduction accumulators

// ---------------------------------------------------------------------------
// small helpers
// ---------------------------------------------------------------------------
__device__ __forceinline__ float4 f44(float v) { return make_float4(v, v, v, v); }

__device__ __forceinline__ float4 min4(float4 a, float4 b) {
    return make_float4(fminf(a.x, b.x), fminf(a.y, b.y), fminf(a.z, b.z), fminf(a.w, b.w));
}
__device__ __forceinline__ float4 max4(float4 a, float4 b) {
    return make_float4(fmaxf(a.x, b.x), fmaxf(a.y, b.y), fmaxf(a.z, b.z), fmaxf(a.w, b.w));
}
__device__ __forceinline__ float4 vmin3(float4 a, float4 b, float4 c) { return min4(min4(a, b), c); }
__device__ __forceinline__ float4 vmax3(float4 a, float4 b, float4 c) { return max4(max4(a, b), c); }

// horizontal 3-tap min across the warp-wide row (lane holds 4 adjacent cols)
__device__ __forceinline__ float4 hmin3(float4 v, int lane) {
    float L = __shfl_up_sync(0xffffffffu, v.w, 1);
    float R = __shfl_down_sync(0xffffffffu, v.x, 1);
    if (lane == 0)  L = INFINITY;
    if (lane == 31) R = INFINITY;
    float m01 = fminf(v.x, v.y), m23 = fminf(v.z, v.w);
    return make_float4(fminf(L, m01), fminf(m01, v.z), fminf(v.y, m23), fminf(m23, R));
}
__device__ __forceinline__ float4 hmax3(float4 v, int lane) {
    float L = __shfl_up_sync(0xffffffffu, v.w, 1);
    float R = __shfl_down_sync(0xffffffffu, v.x, 1);
    if (lane == 0)  L = -INFINITY;
    if (lane == 31) R = -INFINITY;
    float m01 = fmaxf(v.x, v.y), m23 = fmaxf(v.z, v.w);
    return make_float4(fmaxf(L, m01), fmaxf(m01, v.z), fmaxf(v.y, m23), fmaxf(m23, R));
}

__device__ __forceinline__ float4 relu_sub(float4 a, float4 b) {
    return make_float4(fmaxf(0.0f, a.x - b.x), fmaxf(0.0f, a.y - b.y),
                       fmaxf(0.0f, a.z - b.z), fmaxf(0.0f, a.w - b.w));
}
__device__ __forceinline__ float4 maskneg(float4 v, bool ok) {
    return ok ? v : f44(-INFINITY);
}
// skel update: s += relu(d - s*d), per component
__device__ __forceinline__ void skel_upd(float4& s, float4 d) {
    s.x += fmaxf(0.0f, fmaf(-s.x, d.x, d.x));
    s.y += fmaxf(0.0f, fmaf(-s.y, d.y, d.y));
    s.z += fmaxf(0.0f, fmaf(-s.z, d.z, d.z));
    s.w += fmaxf(0.0f, fmaf(-s.w, d.w, d.w));
}

// ---------------------------------------------------------------------------
// Init: p = sigmoid(output); imgA[stream0] = p, imgA[stream1] = target
// ---------------------------------------------------------------------------
__global__ void k_init(const float4* __restrict__ out, const float4* __restrict__ tgt) {
    int i = blockIdx.x * blockDim.x + threadIdx.x;
    int stride = gridDim.x * blockDim.x;
    float4* gp = (float4*)g_p;
    float4* ga = (float4*)g_imgA;
    float4* gb = (float4*)(g_imgA + NIMG * HWSZ);
    const int n4 = NIMG * HWSZ / 4;
    for (; i < n4; i += stride) {
        float4 o = out[i];
        float4 v;
        v.x = 1.0f / (1.0f + expf(-o.x));
        v.y = 1.0f / (1.0f + expf(-o.y));
        v.z = 1.0f / (1.0f + expf(-o.z));
        v.w = 1.0f / (1.0f + expf(-o.w));
        gp[i] = v;
        ga[i] = v;
        gb[i] = tgt[i];
    }
}

// ---------------------------------------------------------------------------
// Warp-sweep open-init:  skel = relu(img - dilate(erode(img)))
// ---------------------------------------------------------------------------
__global__ void __launch_bounds__(SWEEP_BLOCK, 3) k_open_init() {
    const int lane = threadIdx.x & 31;
    const int gw = (blockIdx.x * SWEEP_BLOCK + threadIdx.x) >> 5;
    const int strip = gw % STRIPS;
    const int t = gw / STRIPS;
    const int chunk = t & (CHUNKS - 1);
    const int z = t >> 5;

    const float* __restrict__ src = g_imgA + z * HWSZ;
    float* __restrict__ skel = g_skel + z * HWSZ;

    const int c0 = strip * 120 - 4 + 4 * lane;
    const bool colok = (c0 >= 0) && (c0 < WW);
    const bool stok = (lane >= 1) && (lane <= 30) && (c0 < WW);
    const int r0 = chunk * CHUNK_ROWS;
    const int ylim = r0 + 2;

    int y = r0 - 2;
    const float* srcp = src + y * WW + c0;
    float* const skb = skel + c0;

    float4 ia = f44(INFINITY), ib = f44(INFINITY), ic;
    float4 ha = f44(-INFINITY), hb = f44(-INFINITY), hc;

#define OPEN_STEP(IA, IB, IC, HA, HB, HC)                                      \
    {                                                                          \
        bool ldok = colok && ((unsigned)y < (unsigned)HH);                     \
        IC = ldok ? *(const float4*)srcp : f44(INFINITY);                      \
        float4 e1_ = min4(vmin3(IA, IB, IC), hmin3(IB, lane));                 \
        if (!colok || (unsigned)(y - 1) >= (unsigned)HH) e1_ = f44(-INFINITY); \
        HC = hmax3(e1_, lane);                                                 \
        if (y >= ylim) {                                                       \
            float4 d_ = vmax3(HA, HB, HC);                                     \
            if (stok) {                                                        \
                float4 o_ = relu_sub(IA, d_);                                  \
                *(float4*)(skb + (y - 2) * WW) = o_;                           \
            }                                                                  \
        }                                                                      \
        ++y;                                                                   \
        srcp += WW;                                                            \
    }

#pragma unroll 1
    for (int k = 0; k < 6; ++k) {
        OPEN_STEP(ia, ib, ic, ha, hb, hc);
        OPEN_STEP(ib, ic, ia, hb, hc, ha);
        OPEN_STEP(ic, ia, ib, hc, ha, hb);
    }
    OPEN_STEP(ia, ib, ic, ha, hb, hc);
    OPEN_STEP(ib, ic, ia, hb, hc, ha);
#undef OPEN_STEP
}

// ---------------------------------------------------------------------------
// Fused TWO skeleton iterations per launch, warp-sweep, prefetched loads.
// Per loaded row y:
//   E1[y-1] = erode(I)          (iter1 new img; iter2 input)
//   E2[y-2] = erode(E1)         (shared: dilate-src of iter1 AND iter2 new img)
//   H [y-2] = hmax(mask(E2))    -> D1[y-3] = vmax(H)   -> delta1[y-3] w/ E1[y-3]
//   E3[y-3] = erode(E2)
//   Hb[y-3] = hmax(mask(E3))    -> D2[y-4] = vmax(Hb)  -> delta2[y-4] w/ E2[y-4]
//   row y-4: s = skel; upd(delta1); upd(delta2); store s; store img = E2[y-4]
// Vertical halo 4, horizontal halo 4 (exactly sufficient for depth-2 fusion).
// Vertical +inf masks on E1/E2/E3 are redundant under min (dominated terms);
// only the -inf masks at the hmax feeds are required.
// ---------------------------------------------------------------------------
__global__ void __launch_bounds__(IT2_BLOCK, 4) k_iter2(int flip) {
    const int lane = threadIdx.x & 31;
    const int gw = (blockIdx.x * IT2_BLOCK + threadIdx.x) >> 5;
    const int strip = gw % STRIPS;
    const int t = gw / STRIPS;
    const int chunk = t & (CHUNKS - 1);
    const int z = t >> 5;

    const float* __restrict__ src = (flip ? g_imgB : g_imgA) + z * HWSZ;
    float* __restrict__ dst = (flip ? g_imgA : g_imgB) + z * HWSZ;
    float* __restrict__ skel = g_skel + z * HWSZ;

    const int c0 = strip * 120 - 4 + 4 * lane;
    const bool colok = (c0 >= 0) && (c0 < WW);
    const bool stok = (lane >= 1) && (lane <= 30) && (c0 < WW);
    const int r0 = chunk * CHUNK_ROWS;
    const int yD1 = r0 + 3;    // first step producing delta1 (row y-3 >= r0)
    const int yOUT = r0 + 4;   // first step producing output (row y-4 >= r0)

    int y = r0 - 4;
    // prefetch I[r0-4]; srcp then points at the NEXT row to load (y+1)
    float4 pf;
    {
        bool ldok = colok && ((unsigned)y < (unsigned)HH);
        pf = ldok ? __ldcs((const float4*)(src + y * WW + c0)) : f44(INFINITY);
    }
    const float* srcp = src + (y + 1) * WW + c0;
    float* const skb = skel + c0;
    float* const dsb = dst + c0;

    float4 ia = f44(INFINITY), ib = f44(INFINITY), ic;       // I ring
    float4 ea = f44(INFINITY), eb = f44(INFINITY), ec;       // E1 ring
    float4 fa = f44(INFINITY), fb = f44(INFINITY), fc;       // E2 ring
    float4 ha = f44(-INFINITY), hb = f44(-INFINITY), hc;     // H ring
    float4 ba = f44(-INFINITY), bb = f44(-INFINITY), bc;     // Hb ring
    float4 dprev = f44(0.0f);                                // delta1[y-4]
    float4 spf = f44(0.0f);                                  // skel prefetch

#define STEP2(IA, IB, IC, EA, EB, EC, FA, FB, FC, HA, HB, HC, BA, BB, BC)      \
    {                                                                          \
        float4 icur = pf;                                                      \
        {                                                                      \
            bool ldok = colok && ((unsigned)(y + 1) < (unsigned)HH);           \
            pf = ldok ? __ldcs((const float4*)srcp) : f44(INFINITY);           \
            srcp += WW;                                                        \
        }                                                                      \
        IC = icur;                                                             \
        EC = min4(vmin3(IA, IB, IC), hmin3(IB, lane));     /* E1[y-1] */       \
        FC = min4(vmin3(EA, EB, EC), hmin3(EB, lane));     /* E2[y-2] */       \
        HC = hmax3(maskneg(FC, colok && (unsigned)(y - 2) < (unsigned)HH),     \
                   lane);                                                      \
        float4 e3_ = min4(vmin3(FA, FB, FC), hmin3(FB, lane)); /* E3[y-3] */   \
        BC = hmax3(maskneg(e3_, colok && (unsigned)(y - 3) < (unsigned)HH),    \
                   lane);                                                      \
        if (y >= yOUT) {                                   /* row y-4 */       \
            float4 D2 = vmax3(BA, BB, BC);                                     \
            if (stok) {                                                        \
                float4 d2 = relu_sub(FA, D2);              /* E2[y-4] */       \
                float4 s = spf;                                                \
                skel_upd(s, dprev);                                            \
                skel_upd(s, d2);                                               \
                __stcs((float4*)(skb + (y - 4) * WW), s);                      \
                __stcs((float4*)(dsb + (y - 4) * WW), FA);                     \
            }                                                                  \
        }                                                                      \
        if (y >= yD1) {                                    /* delta1 y-3 */    \
            float4 D1 = vmax3(HA, HB, HC);                                     \
            dprev = relu_sub(EA, D1);                      /* E1[y-3] */       \
            if (stok && (unsigned)(y - 3) < (unsigned)HH)                      \
                spf = __ldcs((const float4*)(skb + (y - 3) * WW));             \
        }                                                                      \
        ++y;                                                                   \
    }

    // 24 steps = 8 groups of 3 (ring rotation by argument permutation)
#pragma unroll 1
    for (int k = 0; k < 8; ++k) {
        STEP2(ia, ib, ic, ea, eb, ec, fa, fb, fc, ha, hb, hc, ba, bb, bc);
        STEP2(ib, ic, ia, eb, ec, ea, fb, fc, fa, hb, hc, ha, bb, bc, ba);
        STEP2(ic, ia, ib, ec, ea, eb, fc, fa, fb, hc, ha, hb, bc, ba, bb);
    }
#undef STEP2
}

// ---------------------------------------------------------------------------
// Reductions
// ---------------------------------------------------------------------------
__global__ void k_zero() {
    int t = threadIdx.x;
    if (t < NIMG * 7) ((double*)g_sums)[t] = 0.0;
}

__global__ void k_reduce(const float* __restrict__ tgt) {
    const int n = blockIdx.y;
    const float4* __restrict__ sp = (const float4*)(g_skel + n * HWSZ);
    const float4* __restrict__ sl = (const float4*)(g_skel + (NIMG + n) * HWSZ);
    const float4* __restrict__ pp = (const float4*)(g_p + n * HWSZ);
    const float4* __restrict__ tt = (const float4*)(tgt + n * HWSZ);
    const int n4 = HWSZ / 4;

    double a0 = 0, a1 = 0, a2 = 0, a3 = 0, a4 = 0, a5 = 0, a6 = 0;
    for (int i = blockIdx.x * blockDim.x + threadIdx.x; i < n4;
         i += gridDim.x * blockDim.x) {
        float4 s1 = sp[i], s2 = sl[i], pv = pp[i], tv = tt[i];
        a0 += (double)(s1.x * tv.x + s1.y * tv.y + s1.z * tv.z + s1.w * tv.w);
        a1 += (double)(s1.x + s1.y + s1.z + s1.w);
        a2 += (double)(s2.x * pv.x + s2.y * pv.y + s2.z * pv.z + s2.w * pv.w);
        a3 += (double)(s2.x + s2.y + s2.z + s2.w);
        a4 += (double)(pv.x * tv.x + pv.y * tv.y + pv.z * tv.z + pv.w * tv.w);
        a5 += (double)(pv.x + pv.y + pv.z + pv.w);
        a6 += (double)(tv.x + tv.y + tv.z + tv.w);
    }
#pragma unroll
    for (int o = 16; o > 0; o >>= 1) {
        a0 += __shfl_down_sync(0xffffffffu, a0, o);
        a1 += __shfl_down_sync(0xffffffffu, a1, o);
        a2 += __shfl_down_sync(0xffffffffu, a2, o);
        a3 += __shfl_down_sync(0xffffffffu, a3, o);
        a4 += __shfl_down_sync(0xffffffffu, a4, o);
        a5 += __shfl_down_sync(0xffffffffu, a5, o);
        a6 += __shfl_down_sync(0xffffffffu, a6, o);
    }
    if ((threadIdx.x & 31) == 0) {
        atomicAdd(&g_sums[n][0], a0);
        atomicAdd(&g_sums[n][1], a1);
        atomicAdd(&g_sums[n][2], a2);
        atomicAdd(&g_sums[n][3], a3);
        atomicAdd(&g_sums[n][4], a4);
        atomicAdd(&g_sums[n][5], a5);
        atomicAdd(&g_sums[n][6], a6);
    }
}

__global__ void k_final(float* __restrict__ out, int out_size) {
    if (threadIdx.x == 0 && blockIdx.x == 0) {
        const double smooth = 1.0;
        double cl = 0.0, dice = 0.0;
        for (int n = 0; n < NIMG; n++) {
            double A = g_sums[n][0], B = g_sums[n][1], C = g_sums[n][2],
                   D = g_sums[n][3], E = g_sums[n][4], F = g_sums[n][5],
                   G = g_sums[n][6];
            double tprec = (A + smooth) / (B + smooth);
            double tsens = (C + smooth) / (D + smooth);
            cl += 1.0 - 2.0 * tprec * tsens / (tprec + tsens);
            dice += 1.0 - 2.0 * (E + smooth) / (F + G + smooth);
        }
        cl /= NIMG;
        dice /= NIMG;
        float loss = (float)(0.7 * dice + 0.3 * cl);
        for (int i = 0; i < out_size; i++) out[i] = loss;
    }
}

// ---------------------------------------------------------------------------
extern "C" void kernel_launch(void* const* d_in, const int* in_sizes, int n_in,
                              void* d_out, int out_size) {
    const float* output = (const float*)d_in[0];
    const float* target = (const float*)d_in[1];
    float* out = (float*)d_out;

    k_init<<<1024, 256>>>((const float4*)output, (const float4*)target);

    k_open_init<<<SWEEP_GRID, SWEEP_BLOCK>>>();

    // 50 iterations = 25 fused-2 launches
    for (int j = 0; j < NITER / 2; ++j) {
        k_iter2<<<IT2_GRID, IT2_BLOCK>>>(j & 1);
    }

    k_zero<<<1, 64>>>();
    k_reduce<<<dim3(32, NIMG), 256>>>(target);
    k_final<<<1, 32>>>(out, out_size);
}